// round 1
// baseline (speedup 1.0000x reference)
#include <cuda_runtime.h>
#include <cuda_pipeline.h>
#include <math.h>

// Problem dims
#define Bz 64
#define Tz 128
#define Sz 100
#define Az 16
#define Hz 120
#define G4 480      // 4*H
#define KTOT 136    // A + H
// LSTM kernel config
#define NROW 50     // rows per block (6400 = 128 * 50)
#define NBLK 128
#define NTH 256
#define TM 5
#define TQ 5
#define ROWPAD 51
#define KTILE 17
#define NTILE 8     // 8 * 17 = 136
// MLP1 config
#define KCH 79
#define NCHUNK 128  // 128 * 79 = 10112 >= 10000

#define SMEM_BYTES ((KTOT * ROWPAD + 2 * KTILE * G4 + G4) * 4)

// ---------------- scratch (static device allocations, allowed) ----------------
__device__ float g_Wc[KTOT * G4];          // combined transposed weights [k][j]
__device__ float g_bias[G4];               // b_ih + b_hh
__device__ float g_W2t[10000 * 256];       // W2 transposed [k][o]
__device__ float g_s[Bz * Sz];             // scores
__device__ float g_foo[Bz * Sz * Sz];      // p_hat flattened
__device__ float g_part[NCHUNK * Bz * 256];// MLP1 partials
__device__ float g_z1[Bz * 256];           // relu(MLP1)

__device__ __forceinline__ float sigm(float x) {
    return __fdividef(1.f, 1.f + __expf(-x));
}
__device__ __forceinline__ float tanh_fast(float x) {
    return __fdividef(2.f, 1.f + __expf(-2.f * x)) - 1.f;
}

// ---------------- prep: weight transpose / combine ----------------
__global__ void prep_kernel(const float* __restrict__ Wih,
                            const float* __restrict__ Whh,
                            const float* __restrict__ bih,
                            const float* __restrict__ bhh,
                            const float* __restrict__ W2) {
    int idx = blockIdx.x * blockDim.x + threadIdx.x;
    int stride = gridDim.x * blockDim.x;
    for (int i = idx; i < KTOT * G4; i += stride) {
        int k = i / G4, j = i - k * G4;
        g_Wc[i] = (k < Az) ? Wih[j * Az + k] : Whh[j * Hz + (k - Az)];
    }
    for (int i = idx; i < G4; i += stride) g_bias[i] = bih[i] + bhh[i];
    for (int i = idx; i < 10000 * 256; i += stride) {
        int k = i >> 8, o = i & 255;
        g_W2t[i] = W2[o * 10000 + k];
    }
}

// ---------------- LSTM: persistent per-row-group, 128 steps ----------------
__global__ void __launch_bounds__(NTH, 1)
lstm_kernel(const float* __restrict__ x,
            const float* __restrict__ w_lin,
            const float* __restrict__ b_lin) {
    extern __shared__ float smf[];
    float* hx = smf;                          // [KTOT][ROWPAD]: k<16 = x_t, else h
    float* wt = smf + KTOT * ROWPAD;          // [2][KTILE*G4] W double buffer
    float* bias_sm = wt + 2 * KTILE * G4;     // [G4]

    const int tid = threadIdx.x;
    const int r0 = blockIdx.x * NROW;

    for (int i = tid; i < G4; i += NTH) bias_sm[i] = g_bias[i];
    for (int i = tid; i < Hz * ROWPAD; i += NTH) hx[Az * ROWPAD + i] = 0.f;

    // x(t=0) transposed into hx[0..15][row]
    for (int i = tid; i < NROW * 4; i += NTH) {
        int m = i >> 2, p = i & 3;
        int r = r0 + m;
        int b = r / Sz, s = r - b * Sz;
        float4 v = *reinterpret_cast<const float4*>(
            x + (((size_t)b * Tz + 0) * Sz + s) * Az + p * 4);
        hx[(p * 4 + 0) * ROWPAD + m] = v.x;
        hx[(p * 4 + 1) * ROWPAD + m] = v.y;
        hx[(p * 4 + 2) * ROWPAD + m] = v.z;
        hx[(p * 4 + 3) * ROWPAD + m] = v.w;
    }

    const bool act = tid < 240;
    const int rowgrp = tid / 24;     // 0..9
    const int qgrp = tid - rowgrp * 24;  // 0..23
    const int m0 = rowgrp * TM;
    const int q0 = qgrp * TQ;

    float c[TM][TQ];
    #pragma unroll
    for (int i = 0; i < TM; i++)
        #pragma unroll
        for (int u = 0; u < TQ; u++) c[i][u] = 0.f;

    __syncthreads();

    for (int t = 0; t < Tz; ++t) {
        float acc[TM][TQ][4];
        if (act) {
            #pragma unroll
            for (int g = 0; g < 4; g++)
                #pragma unroll
                for (int u = 0; u < TQ; u++) {
                    float bv = bias_sm[g * Hz + q0 + u];
                    #pragma unroll
                    for (int i = 0; i < TM; i++) acc[i][u][g] = bv;
                }
        }

        // prefetch W tile 0
        {
            const float* src = g_Wc;
            float* dst = wt;
            for (int i = tid; i < (KTILE * G4) / 4; i += NTH)
                __pipeline_memcpy_async(dst + i * 4, src + i * 4, 16);
            __pipeline_commit();
        }

        for (int tt = 0; tt < NTILE; ++tt) {
            __pipeline_wait_prior(0);
            __syncthreads();  // tile tt resident + everyone done with other buffer
            if (tt + 1 < NTILE) {
                const float* src = g_Wc + (tt + 1) * (KTILE * G4);
                float* dst = wt + ((tt + 1) & 1) * (KTILE * G4);
                for (int i = tid; i < (KTILE * G4) / 4; i += NTH)
                    __pipeline_memcpy_async(dst + i * 4, src + i * 4, 16);
                __pipeline_commit();
            }
            if (act) {
                const float* wb = wt + (tt & 1) * (KTILE * G4);
                const int kb = tt * KTILE;
                #pragma unroll 1
                for (int k = 0; k < KTILE; ++k) {
                    float a[TM];
                    const float* hrow = hx + (kb + k) * ROWPAD + m0;
                    #pragma unroll
                    for (int i = 0; i < TM; i++) a[i] = hrow[i];
                    const float* wk = wb + k * G4 + q0;
                    #pragma unroll
                    for (int g = 0; g < 4; g++) {
                        #pragma unroll
                        for (int u = 0; u < TQ; u++) {
                            float w = wk[g * Hz + u];
                            #pragma unroll
                            for (int i = 0; i < TM; i++)
                                acc[i][u][g] = fmaf(a[i], w, acc[i][u][g]);
                        }
                    }
                }
            }
        }

        float hreg[TM][TQ];
        if (act) {
            #pragma unroll
            for (int i = 0; i < TM; i++)
                #pragma unroll
                for (int u = 0; u < TQ; u++) {
                    float ig = sigm(acc[i][u][0]);
                    float fg = sigm(acc[i][u][1]);
                    float gg = tanh_fast(acc[i][u][2]);
                    float og = sigm(acc[i][u][3]);
                    float cc = fmaf(fg, c[i][u], ig * gg);
                    c[i][u] = cc;
                    hreg[i][u] = og * tanh_fast(cc);
                }
        }
        __syncthreads();  // all GEMM reads of hx complete before overwrite
        if (act) {
            #pragma unroll
            for (int u = 0; u < TQ; u++)
                #pragma unroll
                for (int i = 0; i < TM; i++)
                    hx[(Az + q0 + u) * ROWPAD + m0 + i] = hreg[i][u];
        }
        if (t + 1 < Tz) {
            for (int i = tid; i < NROW * 4; i += NTH) {
                int m = i >> 2, p = i & 3;
                int r = r0 + m;
                int b = r / Sz, s = r - b * Sz;
                float4 v = *reinterpret_cast<const float4*>(
                    x + (((size_t)b * Tz + (t + 1)) * Sz + s) * Az + p * 4);
                hx[(p * 4 + 0) * ROWPAD + m] = v.x;
                hx[(p * 4 + 1) * ROWPAD + m] = v.y;
                hx[(p * 4 + 2) * ROWPAD + m] = v.z;
                hx[(p * 4 + 3) * ROWPAD + m] = v.w;
            }
        }
        // next-iteration tt=0 wait+sync orders these writes vs. next GEMM reads
    }

    __syncthreads();
    // score head: s = h_last . w_lin + b_lin   (h_last lives in hx)
    if (tid < NROW) {
        float sv = b_lin[0];
        #pragma unroll 4
        for (int q = 0; q < Hz; q++)
            sv = fmaf(w_lin[q], hx[(Az + q) * ROWPAD + tid], sv);
        g_s[r0 + tid] = sv;
    }
}

// ---------------- NeuralSort relaxed permutation + softmax ----------------
__global__ void sort_kernel() {
    __shared__ float s_sm[Sz];
    __shared__ float rs_sm[Sz];
    int b = blockIdx.x, tid = threadIdx.x;
    if (tid < Sz) s_sm[tid] = g_s[b * Sz + tid];
    __syncthreads();
    if (tid < Sz) {
        float si = s_sm[tid], sum = 0.f;
        for (int j = 0; j < Sz; j++) sum += fabsf(si - s_sm[j]);
        rs_sm[tid] = sum;
    }
    __syncthreads();
    int warp = tid >> 5, lane = tid & 31;
    for (int i = warp; i < Sz; i += 4) {
        float scal = (float)(Sz - 1 - 2 * i);  // 99 - 2i
        float v[4], e[4];
        float mx = -INFINITY;
        #pragma unroll
        for (int cc = 0; cc < 4; cc++) {
            int j = lane + 32 * cc;
            v[cc] = (j < Sz) ? (s_sm[j] * scal - rs_sm[j]) * 0.2f : -INFINITY;
            mx = fmaxf(mx, v[cc]);
        }
        #pragma unroll
        for (int o = 16; o; o >>= 1) mx = fmaxf(mx, __shfl_xor_sync(0xffffffffu, mx, o));
        float sum = 0.f;
        #pragma unroll
        for (int cc = 0; cc < 4; cc++) {
            int j = lane + 32 * cc;
            e[cc] = (j < Sz) ? __expf(v[cc] - mx) : 0.f;
            sum += e[cc];
        }
        #pragma unroll
        for (int o = 16; o; o >>= 1) sum += __shfl_xor_sync(0xffffffffu, sum, o);
        float inv = __fdividef(1.f, sum);
        #pragma unroll
        for (int cc = 0; cc < 4; cc++) {
            int j = lane + 32 * cc;
            if (j < Sz) g_foo[(size_t)b * (Sz * Sz) + i * Sz + j] = e[cc] * inv;
        }
    }
}

// ---------------- MLP1 partial GEMM: K-split over 128 chunks ----------------
__global__ void __launch_bounds__(256) mlp1_kernel() {
    int c = blockIdx.x, tid = threadIdx.x;
    int k0 = c * KCH;
    int kend = min(k0 + KCH, 10000);
    int bg = tid >> 5;   // 8 row groups (of 8 batches)
    int og = tid & 31;   // 32 col groups (of 8 outputs)
    float acc[8][8];
    #pragma unroll
    for (int i = 0; i < 8; i++)
        #pragma unroll
        for (int j = 0; j < 8; j++) acc[i][j] = 0.f;
    const float* fooB = g_foo + (size_t)(bg * 8) * 10000;
    for (int k = k0; k < kend; ++k) {
        float a[8];
        #pragma unroll
        for (int i = 0; i < 8; i++) a[i] = fooB[(size_t)i * 10000 + k];
        float4 w0 = *reinterpret_cast<const float4*>(g_W2t + (size_t)k * 256 + og * 8);
        float4 w1 = *reinterpret_cast<const float4*>(g_W2t + (size_t)k * 256 + og * 8 + 4);
        float w[8] = {w0.x, w0.y, w0.z, w0.w, w1.x, w1.y, w1.z, w1.w};
        #pragma unroll
        for (int i = 0; i < 8; i++)
            #pragma unroll
            for (int j = 0; j < 8; j++) acc[i][j] = fmaf(a[i], w[j], acc[i][j]);
    }
    #pragma unroll
    for (int i = 0; i < 8; i++)
        #pragma unroll
        for (int j = 0; j < 8; j++)
            g_part[((size_t)c * 64 + bg * 8 + i) * 256 + og * 8 + j] = acc[i][j];
}

// ---------------- reduce partials + bias + relu ----------------
__global__ void reduce_kernel(const float* __restrict__ b2) {
    int b = blockIdx.x, o = threadIdx.x;
    float s = b2[o];
    for (int c = 0; c < NCHUNK; ++c) s += g_part[((size_t)c * 64 + b) * 256 + o];
    g_z1[b * 256 + o] = fmaxf(s, 0.f);
}

// ---------------- MLP2 + final softmax ----------------
__global__ void mlp2_kernel(const float* __restrict__ W3,
                            const float* __restrict__ b3,
                            float* __restrict__ out) {
    __shared__ float z1s[256];
    __shared__ float zs[Sz];
    __shared__ float s_mx, s_sum;
    int b = blockIdx.x, tid = threadIdx.x;  // 128 threads
    z1s[tid] = g_z1[b * 256 + tid];
    z1s[tid + 128] = g_z1[b * 256 + tid + 128];
    __syncthreads();
    if (tid < Sz) {
        float accv = b3[tid];
        const float* wr = W3 + tid * 256;
        #pragma unroll 4
        for (int k = 0; k < 256; k++) accv = fmaf(z1s[k], wr[k], accv);
        zs[tid] = accv;
    }
    __syncthreads();
    if (tid == 0) {
        float mx = -INFINITY;
        for (int j = 0; j < Sz; j++) mx = fmaxf(mx, zs[j]);
        float sum = 0.f;
        for (int j = 0; j < Sz; j++) sum += __expf(zs[j] - mx);
        s_mx = mx;
        s_sum = sum;
    }
    __syncthreads();
    if (tid < Sz)
        out[b * Sz + tid] = __expf(zs[tid] - s_mx) * __fdividef(1.f, s_sum);
}

// ---------------- launch ----------------
extern "C" void kernel_launch(void* const* d_in, const int* in_sizes, int n_in,
                              void* d_out, int out_size) {
    const float* x    = (const float*)d_in[0];
    const float* Wih  = (const float*)d_in[1];
    const float* Whh  = (const float*)d_in[2];
    const float* bih  = (const float*)d_in[3];
    const float* bhh  = (const float*)d_in[4];
    const float* wlin = (const float*)d_in[5];
    const float* blin = (const float*)d_in[6];
    const float* W2   = (const float*)d_in[7];
    const float* b2   = (const float*)d_in[8];
    const float* W3   = (const float*)d_in[9];
    const float* b3   = (const float*)d_in[10];
    float* out = (float*)d_out;
    (void)in_sizes; (void)n_in; (void)out_size;

    cudaFuncSetAttribute(lstm_kernel,
                         cudaFuncAttributeMaxDynamicSharedMemorySize, SMEM_BYTES);

    prep_kernel<<<512, 256>>>(Wih, Whh, bih, bhh, W2);
    lstm_kernel<<<NBLK, NTH, SMEM_BYTES>>>(x, wlin, blin);
    sort_kernel<<<Bz, 128>>>();
    mlp1_kernel<<<NCHUNK, 256>>>();
    reduce_kernel<<<Bz, 256>>>(b2);
    mlp2_kernel<<<Bz, 128>>>(W3, b3, out);
}